// round 17
// baseline (speedup 1.0000x reference)
#include <cuda_runtime.h>
#include <cuda_fp16.h>
#include <cstdint>

#define BH   32
#define S    2048
#define D    64
#define TQ   16
#define NT   512
#define QSP  68
#define RMP  18
#define PSTR 1036            // p hi/lo row stride (u32)
#define NTILES 16            // 128-row tiles
#define NEG_INF_F (-1e10f)
#define SCALE     (0.125f)

// smem layout (u32 units)
#define OFF_P     0            // p hi/lo: 16 rows x PSTR, two planes
#define OFF_PLO   16576
#define OFF_KW    33152        // per-warp slice buffers: 16 warps x 4 stages x 288 u32
#define OFF_QS    51584
#define OFF_RSUM  52672
#define OFF_INVS  52960
#define SMEM_U32  52976
#define SMEM_BYTES (SMEM_U32 * 4)

#define STG 288                // per-stage u32 (hi only)
#define WBUF_STRIDE 1152       // 4 stages x 288

// pre-converted fp16 operands (hi only) in global scratch
__device__ __half g_Khi[BH * S * D];
__device__ __half g_Vthi[BH * D * S];   // transposed [bh][d][s]

__device__ __forceinline__ uint32_t pack_h2(float x, float y) {
    __half2 h = __floats2half2_rn(x, y);
    return *reinterpret_cast<uint32_t*>(&h);
}
__device__ __forceinline__ float2 unpack_h2(uint32_t u) {
    __half2 h = *reinterpret_cast<__half2*>(&u);
    return __half22float2(h);
}
__device__ __forceinline__ void split2(float x, float y, uint32_t& hi, uint32_t& lo) {
    hi = pack_h2(x, y);
    float2 hf = unpack_h2(hi);
    lo = pack_h2(x - hf.x, y - hf.y);
}

__device__ __forceinline__ void mma_f16(float* c, const uint32_t* a, uint32_t b0, uint32_t b1) {
    asm volatile(
        "mma.sync.aligned.m16n8k16.row.col.f32.f16.f16.f32 "
        "{%0,%1,%2,%3},{%4,%5,%6,%7},{%8,%9},{%0,%1,%2,%3};"
        : "+f"(c[0]), "+f"(c[1]), "+f"(c[2]), "+f"(c[3])
        : "r"(a[0]), "r"(a[1]), "r"(a[2]), "r"(a[3]), "r"(b0), "r"(b1));
}

__device__ __forceinline__ void cpa16(uint32_t* dst, const void* src) {
    uint32_t d = (uint32_t)__cvta_generic_to_shared(dst);
    asm volatile("cp.async.cg.shared.global [%0], [%1], 16;" :: "r"(d), "l"(src));
}
__device__ __forceinline__ void cp_commit() { asm volatile("cp.async.commit_group;"); }
__device__ __forceinline__ void cp_wait3() { asm volatile("cp.async.wait_group 3;" ::: "memory"); }
__device__ __forceinline__ void cp_wait2() { asm volatile("cp.async.wait_group 2;" ::: "memory"); }
__device__ __forceinline__ void cp_wait1() { asm volatile("cp.async.wait_group 1;" ::: "memory"); }
__device__ __forceinline__ void cp_wait0() { asm volatile("cp.async.wait_group 0;" ::: "memory"); }

// ---------------- pre-kernels ----------------
__global__ void conv_k_kernel(const float* __restrict__ K) {
    int i = blockIdx.x * blockDim.x + threadIdx.x;
    const float4* src = (const float4*)K + i * 2;
    float4 a = __ldcs(src);
    float4 b = __ldcs(src + 1);
    uint4 o;
    o.x = pack_h2(a.x, a.y);
    o.y = pack_h2(a.z, a.w);
    o.z = pack_h2(b.x, b.y);
    o.w = pack_h2(b.z, b.w);
    ((uint4*)g_Khi)[i] = o;
}

__global__ void conv_vt_kernel(const float* __restrict__ V) {
    __shared__ float tile[64][65];
    int bh = blockIdx.y, s0 = blockIdx.x * 64;
    int tid = threadIdx.x;
    #pragma unroll
    for (int i = 0; i < 16; ++i) {
        int r = i * 4 + (tid >> 6), d = tid & 63;
        tile[r][d] = __ldcs(&V[((size_t)bh * S + s0 + r) * D + d]);
    }
    __syncthreads();
    #pragma unroll
    for (int i = 0; i < 2; ++i) {
        int dr  = i * 32 + (tid >> 3);
        int scb = (tid & 7) * 8;
        uint4 o;
        o.x = pack_h2(tile[scb + 0][dr], tile[scb + 1][dr]);
        o.y = pack_h2(tile[scb + 2][dr], tile[scb + 3][dr]);
        o.z = pack_h2(tile[scb + 4][dr], tile[scb + 5][dr]);
        o.w = pack_h2(tile[scb + 6][dr], tile[scb + 7][dr]);
        *(uint4*)(g_Vthi + ((size_t)bh * D + dr) * S + s0 + scb) = o;
    }
}

// ---------------- main kernel ----------------
__global__ __launch_bounds__(NT, 1)
void dist_attn_kernel(const float* __restrict__ Q,
                      const float* __restrict__ dist,
                      const int* __restrict__ mask,
                      float* __restrict__ ctx,
                      float* __restrict__ attn)
{
    extern __shared__ uint32_t smu[];
    uint32_t* phi  = smu + OFF_P;
    uint32_t* plo  = smu + OFF_PLO;
    float*    Qs   = (float*)(smu + OFF_QS);
    float*    rsum = (float*)(smu + OFF_RSUM);
    float*    invs = (float*)(smu + OFF_INVS);

    const int t    = threadIdx.x;
    const int warp = t >> 5;
    const int lane = t & 31;
    const int gid  = lane >> 2;
    const int tig  = lane & 3;
    const int bh = blockIdx.y;
    const int q0 = blockIdx.x * TQ;
    const size_t rowbase = (size_t)bh * S;

    uint32_t* wbuf = smu + OFF_KW + warp * WBUF_STRIDE;

    const __half* Khi_b = g_Khi + (size_t)bh * S * D;

    // per-warp K slice: 8 rows x 64 halves (hi), one tile
    auto load_k_slice = [&](int stage, int tile) {
        uint32_t* dst = wbuf + stage * STG;
        #pragma unroll
        for (int i = 0; i < 2; ++i) {
            int idx = lane + i * 32;        // 0..63
            int r = idx >> 3, c = idx & 7;
            const __half* src = Khi_b + ((tile * 128 + warp * 8 + r) * D + c * 8);
            cpa16(dst + r * 36 + c * 4, src);
        }
        cp_commit();
    };

    // prologue: 4-deep
    load_k_slice(0, 0);
    load_k_slice(1, 1);
    load_k_slice(2, 2);
    load_k_slice(3, 3);

    if (t < 256) {
        const float4 v = ((const float4*)(Q + (rowbase + q0) * D))[t];
        int qr = t >> 4, d4 = t & 15;
        *(float4*)(Qs + qr * QSP + d4 * 4) = v;
    }
    __syncthreads();

    // Q A-fragments (fp16 hi/lo), 4 k16-chunks
    uint32_t qa_hi[4][4], qa_lo[4][4];
    #pragma unroll
    for (int c = 0; c < 4; ++c) {
        const float* qg  = Qs + gid * QSP       + c * 16 + 2 * tig;
        const float* qg8 = Qs + (gid + 8) * QSP + c * 16 + 2 * tig;
        split2(qg[0],  qg[1],  qa_hi[c][0], qa_lo[c][0]);
        split2(qg8[0], qg8[1], qa_hi[c][1], qa_lo[c][1]);
        split2(qg[8],  qg[9],  qa_hi[c][2], qa_lo[c][2]);
        split2(qg8[8], qg8[9], qa_hi[c][3], qa_lo[c][3]);
    }

    // ====== Phase 1: QK^T + dist/mask/scale + MAX-FREE exp + p store + row-sums ======
    const size_t rg0 = (rowbase + q0 + gid) * S;
    const size_t rg8 = (rowbase + q0 + gid + 8) * S;
    const int colw = warp * 8 + 2 * tig;

    // 3-deep dist/mask register pipeline (streaming, evict-first)
    float2 dd0[3], dd1[3];
    int2   mm0[3], mm1[3];
    #pragma unroll
    for (int p = 0; p < 3; ++p) {
        int col = p * 128 + colw;
        dd0[p] = __ldcs((const float2*)(dist + rg0 + col));
        dd1[p] = __ldcs((const float2*)(dist + rg8 + col));
        mm0[p] = __ldcs((const int2*)(mask + rg0 + col));
        mm1[p] = __ldcs((const int2*)(mask + rg8 + col));
    }

    float sum0 = 0.f, sum1 = 0.f;
    #pragma unroll
    for (int p = 0; p < NTILES; ++p) {
        const int st = p & 3;
        const int rp = p % 3;

        float2 d0 = dd0[rp], d1 = dd1[rp];
        int2   k0 = mm0[rp], k1 = mm1[rp];
        if (p + 3 < NTILES) {
            int col = (p + 3) * 128 + colw;
            dd0[rp] = __ldcs((const float2*)(dist + rg0 + col));
            dd1[rp] = __ldcs((const float2*)(dist + rg8 + col));
            mm0[rp] = __ldcs((const int2*)(mask + rg0 + col));
            mm1[rp] = __ldcs((const int2*)(mask + rg8 + col));
        }

        if      (p < NTILES - 3)  cp_wait3();
        else if (p == NTILES - 3) cp_wait2();
        else if (p == NTILES - 2) cp_wait1();
        else                      cp_wait0();
        __syncwarp();

        float aHH[4] = {0,0,0,0}, aLH[4] = {0,0,0,0};
        const uint32_t* kb = wbuf + st * STG + gid * 36 + tig;
        #pragma unroll
        for (int c = 0; c < 4; ++c) {
            uint32_t b0h = kb[c * 8], b1h = kb[c * 8 + 4];
            mma_f16(aHH, qa_hi[c], b0h, b1h);
            mma_f16(aLH, qa_lo[c], b0h, b1h);
        }
        __syncwarp();
        if (p + 4 < NTILES) load_k_slice(st, p + 4);

        float s0 = aHH[0] + aLH[0];
        float s1 = aHH[1] + aLH[1];
        float s2 = aHH[2] + aLH[2];
        float s3 = aHH[3] + aLH[3];
        s0 = k0.x ? NEG_INF_F : d0.x * s0 * SCALE;
        s1 = k0.y ? NEG_INF_F : d0.y * s1 * SCALE;
        s2 = k1.x ? NEG_INF_F : d1.x * s2 * SCALE;
        s3 = k1.y ? NEG_INF_F : d1.y * s3 * SCALE;

        // max-free softmax numerator (masked -> exp underflows to exactly 0)
        float p0 = __expf(s0), p1 = __expf(s1);
        float p2 = __expf(s2), p3 = __expf(s3);
        sum0 += p0 + p1;
        sum1 += p2 + p3;

        uint32_t h0, l0, h1, l1;
        split2(p0, p1, h0, l0);
        split2(p2, p3, h1, l1);
        const int pb = p * 64 + warp * 4 + tig;
        phi[gid * PSTR + pb]       = h0;
        plo[gid * PSTR + pb]       = l0;
        phi[(gid + 8) * PSTR + pb] = h1;
        plo[(gid + 8) * PSTR + pb] = l1;
    }
    // reduce row-sums over tig, stash per-warp partials
    #pragma unroll
    for (int o = 1; o <= 2; o <<= 1) {
        sum0 += __shfl_xor_sync(0xffffffffu, sum0, o);
        sum1 += __shfl_xor_sync(0xffffffffu, sum1, o);
    }
    if (tig == 0) {
        rsum[warp * RMP + gid]     = sum0;
        rsum[warp * RMP + gid + 8] = sum1;
    }

    // V^T slice prefetch for tiles 0..3 — before the barrier
    const int kg = warp & 7;
    const int nh = warp >> 3;
    const __half* Vthi_b = g_Vthi + ((size_t)bh * D + nh * 32) * S;
    auto load_v_slice = [&](int stage, int tile) {
        uint32_t* dst = wbuf + stage * STG;
        int pcol = tile * 128 + kg * 16;
        #pragma unroll
        for (int i = 0; i < 2; ++i) {
            int idx = lane + i * 32;   // 0..63
            int r = idx >> 1, c = idx & 1;
            const __half* src = Vthi_b + ((size_t)r * S + pcol + c * 8);
            cpa16(dst + (r >> 2) * 36 + (r & 3) * 8 + c * 4, src);
        }
        cp_commit();
    };
    load_v_slice(0, 0);
    load_v_slice(1, 1);
    load_v_slice(2, 2);
    load_v_slice(3, 3);

    __syncthreads();   // barrier #1: p overlay + partial sums complete

    // row-sum finalize: warp q reduces its own row's 16 partials
    float invW;
    {
        float sm_ = (lane < 16) ? rsum[lane * RMP + warp] : 0.f;
        #pragma unroll
        for (int o = 16; o > 0; o >>= 1)
            sm_ += __shfl_xor_sync(0xffffffffu, sm_, o);
        invW = 1.f / sm_;
        if (lane == 0) invs[warp] = invW;
    }

    // ============ Phase 3: p @ V (2-term) + coalesced streaming attn write ============
    {
        float4* attnRowW = (float4*)(attn + (rowbase + q0 + warp) * S);

        float acc[4][4];
        #pragma unroll
        for (int i = 0; i < 4; ++i)
            #pragma unroll
            for (int j = 0; j < 4; ++j) acc[i][j] = 0.f;

        #pragma unroll
        for (int p = 0; p < NTILES; ++p) {
            const int st = p & 3;

            if      (p < NTILES - 3)  cp_wait3();
            else if (p == NTILES - 3) cp_wait2();
            else if (p == NTILES - 2) cp_wait1();
            else                      cp_wait0();
            __syncwarp();

            // coalesced attn chunk: warp w writes row w, this tile's 128 cols
            {
                int pb = p * 64 + lane * 2;
                uint2 h = *(const uint2*)(phi + warp * PSTR + pb);
                uint2 l = *(const uint2*)(plo + warp * PSTR + pb);
                float2 ha = unpack_h2(h.x), la = unpack_h2(l.x);
                float2 hb = unpack_h2(h.y), lb = unpack_h2(l.y);
                __stcs(attnRowW + p * 32 + lane, make_float4(
                    (ha.x + la.x) * invW, (ha.y + la.y) * invW,
                    (hb.x + lb.x) * invW, (hb.y + lb.y) * invW));
            }

            // A fragments from p hi/lo overlay
            const int pb = p * 64 + kg * 8 + tig;
            uint32_t Ah[4], Al[4];
            Ah[0] = phi[gid * PSTR + pb];
            Ah[1] = phi[(gid + 8) * PSTR + pb];
            Ah[2] = phi[gid * PSTR + pb + 4];
            Ah[3] = phi[(gid + 8) * PSTR + pb + 4];
            Al[0] = plo[gid * PSTR + pb];
            Al[1] = plo[(gid + 8) * PSTR + pb];
            Al[2] = plo[gid * PSTR + pb + 4];
            Al[3] = plo[(gid + 8) * PSTR + pb + 4];

            const uint32_t* vs = wbuf + st * STG;
            #pragma unroll
            for (int nt = 0; nt < 4; ++nt) {
                const uint32_t* vb = vs + (nt * 2 + (gid >> 2)) * 36 + (gid & 3) * 8 + tig;
                uint32_t b0h = vb[0], b1h = vb[4];
                mma_f16(acc[nt], Ah, b0h, b1h);
                mma_f16(acc[nt], Al, b0h, b1h);
            }
            __syncwarp();
            if (p + 4 < NTILES) load_v_slice(st, p + 4);
        }
        __syncthreads();   // barrier #2: reuse per-warp region as reduce scratch

        // split-k reduce: red[kg 8][q 16][68]
        float* red = (float*)(smu + OFF_KW);
        #pragma unroll
        for (int nt = 0; nt < 4; ++nt) {
            int d = nh * 32 + nt * 8 + 2 * tig;
            *(float2*)(red + kg * 1088 + gid * 68 + d) =
                make_float2(acc[nt][0], acc[nt][1]);
            *(float2*)(red + kg * 1088 + (gid + 8) * 68 + d) =
                make_float2(acc[nt][2], acc[nt][3]);
        }
        __syncthreads();   // barrier #3

        #pragma unroll
        for (int o = t; o < TQ * D; o += NT) {
            int q = o >> 6, d = o & 63;
            float s = 0.f;
            #pragma unroll
            for (int g = 0; g < 8; ++g)
                s += red[g * 1088 + q * 68 + d];
            ctx[(rowbase + q0 + q) * D + d] = s * invs[q];
        }
    }
}

extern "C" void kernel_launch(void* const* d_in, const int* in_sizes, int n_in,
                              void* d_out, int out_size)
{
    const float* Q    = (const float*)d_in[0];
    const float* K    = (const float*)d_in[1];
    const float* V    = (const float*)d_in[2];
    const float* dist = (const float*)d_in[3];
    const int*   mask = (const int*)d_in[4];

    float* ctx  = (float*)d_out;
    float* attn = (float*)d_out + (size_t)BH * S * D;

    conv_k_kernel<<<(BH * S * D) / (256 * 8), 256>>>(K);
    {
        dim3 g(S / 64, BH);
        conv_vt_kernel<<<g, 256>>>(V);
    }

    cudaFuncSetAttribute(dist_attn_kernel,
                         cudaFuncAttributeMaxDynamicSharedMemorySize,
                         SMEM_BYTES);

    dim3 grid(S / TQ, BH);
    dist_attn_kernel<<<grid, NT, SMEM_BYTES>>>(Q, dist, mask, ctx, attn);
}